// round 10
// baseline (speedup 1.0000x reference)
#include <cuda_runtime.h>
#include <cuda_fp16.h>
#include <cstdint>

#define NN 100000      // input nodes
#define MM 100000      // output nodes
#define NNZ_C 3200000  // edges (divisible by 32)
#define BB 32          // batch

// Scratch
__device__ __half g_xth[NN * BB];  // x transposed (N, 32) in fp16, 6.4 MB
__device__ float  g_yt[MM * BB];   // y_t[m][b] accumulator, 12.8 MB

// ---------------------------------------------------------------------------
// Dummy no-op kernel (keeps edge_kernel at launch index 3 for ncu capture)
// ---------------------------------------------------------------------------
__global__ void dummy_kernel() {}

// ---------------------------------------------------------------------------
// Zero the accumulator (float4 grid-stride)
// ---------------------------------------------------------------------------
__global__ void zero_yt_kernel() {
    float4* p = reinterpret_cast<float4*>(g_yt);
    const int total = (MM * BB) / 4;
    for (int i = blockIdx.x * blockDim.x + threadIdx.x; i < total;
         i += gridDim.x * blockDim.x) {
        p[i] = make_float4(0.f, 0.f, 0.f, 0.f);
    }
}

// ---------------------------------------------------------------------------
// Transpose x (B, N) -> x_t (N, B) in fp16.
// ---------------------------------------------------------------------------
__global__ void transpose_in_kernel(const float* __restrict__ x) {
    __shared__ float tile[128][33];
    int n0 = blockIdx.x * 128;
    int t = threadIdx.x;
#pragma unroll
    for (int i = 0; i < 4; i++) {
        int idx = i * 256 + t;      // 0..1023
        int b = idx >> 5;           // batch row 0..31
        int q = idx & 31;           // float4 index along n
        int n = n0 + q * 4;
        if (n + 3 < NN) {
            float4 xv = __ldg((const float4*)(x + b * NN + n));
            tile[q * 4 + 0][b] = xv.x;
            tile[q * 4 + 1][b] = xv.y;
            tile[q * 4 + 2][b] = xv.z;
            tile[q * 4 + 3][b] = xv.w;
        } else {
#pragma unroll
            for (int j = 0; j < 4; j++)
                if (n + j < NN) tile[q * 4 + j][b] = x[b * NN + n + j];
        }
    }
    __syncthreads();
#pragma unroll
    for (int i = 0; i < 4; i++) {
        int idx = i * 256 + t;
        int nloc = idx >> 3;        // 0..127
        int b4 = idx & 7;
        int n = n0 + nloc;
        if (n < NN) {
            __half2 h0 = __floats2half2_rn(tile[nloc][b4 * 4 + 0],
                                           tile[nloc][b4 * 4 + 1]);
            __half2 h1 = __floats2half2_rn(tile[nloc][b4 * 4 + 2],
                                           tile[nloc][b4 * 4 + 3]);
            uint2 o;
            o.x = *(const unsigned int*)&h0;
            o.y = *(const unsigned int*)&h1;
            *(uint2*)(g_xth + n * BB + b4 * 4) = o;
        }
    }
}

// ---------------------------------------------------------------------------
// Edge scatter, software-pipelined: per warp, stage ALL 8 gathers (and the
// shuffled per-edge metadata) into registers first, then issue all 8 REDs.
// 32 edges/warp; 8 lanes per edge, float4 slice per lane.
// ---------------------------------------------------------------------------
__global__ void __launch_bounds__(256) edge_kernel(
        const int* __restrict__ src,
        const int* __restrict__ dst,
        const float* __restrict__ vals) {
    int gtid = blockIdx.x * blockDim.x + threadIdx.x;
    int warp_id = gtid >> 5;
    int lane = threadIdx.x & 31;

    int e = warp_id * 32 + lane;
    int   s = __ldg(&src[e]);
    int   d = __ldg(&dst[e]);
    float v = __ldg(&vals[e]);

    int seg = lane & 7;   // which 4-element slice of the 32-wide batch row
    int sub = lane >> 3;  // which of 4 concurrent edges

    const uint2* xt2 = reinterpret_cast<const uint2*>(g_xth);

    uint2 xs[8];
    int   de[8];
    float ve[8];

    // Phase 1: broadcast metadata + launch all gathers (8 independent LDG.64)
#pragma unroll
    for (int j = 0; j < 8; j++) {
        int eidx = j * 4 + sub;
        int se = __shfl_sync(0xffffffffu, s, eidx);
        de[j]  = __shfl_sync(0xffffffffu, d, eidx);
        ve[j]  = __shfl_sync(0xffffffffu, v, eidx);
        xs[j]  = __ldg(&xt2[se * 8 + seg]);
    }

    // Phase 2: convert, scale, scatter
#pragma unroll
    for (int j = 0; j < 8; j++) {
        __half2 h0 = *(const __half2*)&xs[j].x;
        __half2 h1 = *(const __half2*)&xs[j].y;
        float2 f0 = __half22float2(h0);
        float2 f1 = __half22float2(h1);
        float cx = f0.x * ve[j], cy = f0.y * ve[j];
        float cz = f1.x * ve[j], cw = f1.y * ve[j];
        float* p = g_yt + de[j] * BB + seg * 4;
        asm volatile(
            "red.global.add.v4.f32 [%0], {%1, %2, %3, %4};"
            :: "l"(p), "f"(cx), "f"(cy), "f"(cz), "f"(cw)
            : "memory");
    }
}

// ---------------------------------------------------------------------------
// out (B, M) = transpose(y_t (M, B)) + bias. Conflict-free both phases.
// ---------------------------------------------------------------------------
__global__ void transpose_out_kernel(float* __restrict__ out,
                                     const float* __restrict__ bias) {
    __shared__ float tile[32][129];   // [b][m_local]
    int m0 = blockIdx.x * 128;
    int t = threadIdx.x;
#pragma unroll
    for (int i = 0; i < 4; i++) {
        int idx = i * 256 + t;      // 0..1023
        int mloc = idx >> 3;        // 0..127
        int b4 = idx & 7;
        int m = m0 + mloc;
        if (m < MM) {
            float4 yv = *(const float4*)(g_yt + m * BB + b4 * 4);
            float bi = __ldg(&bias[m]);
            tile[b4 * 4 + 0][mloc] = yv.x + bi;
            tile[b4 * 4 + 1][mloc] = yv.y + bi;
            tile[b4 * 4 + 2][mloc] = yv.z + bi;
            tile[b4 * 4 + 3][mloc] = yv.w + bi;
        }
    }
    __syncthreads();
#pragma unroll
    for (int i = 0; i < 16; i++) {
        int idx = i * 256 + t;      // 0..4095
        int b  = idx >> 7;          // 0..31
        int ml = idx & 127;         // 0..127, consecutive within warp
        int m = m0 + ml;
        if (m < MM)
            out[b * MM + m] = tile[b][ml];
    }
}

// ---------------------------------------------------------------------------
extern "C" void kernel_launch(void* const* d_in, const int* in_sizes, int n_in,
                              void* d_out, int out_size) {
    const float* x       = (const float*)d_in[0];   // (B, N, 1)
    const int*   indices = (const int*)d_in[1];     // (2, NNZ)
    const float* vals    = (const float*)d_in[2];   // (NNZ,)
    const float* bias    = (const float*)d_in[3];   // (M, 1)
    float* out = (float*)d_out;                     // (B, M, 1)

    const int* src = indices;
    const int* dst = indices + NNZ_C;

    // Launch order chosen so edge_kernel sits at index 3 (ncu capture slot).
    transpose_in_kernel<<<(NN + 127) / 128, 256>>>(x);   // 0
    zero_yt_kernel<<<1600, 256>>>();                     // 1
    dummy_kernel<<<1, 32>>>();                           // 2
    edge_kernel<<<NNZ_C / 256, 256>>>(src, dst, vals);   // 3
    transpose_out_kernel<<<(MM + 127) / 128, 256>>>(out, bias);  // 4
}

// round 14
// speedup vs baseline: 1.1993x; 1.1993x over previous
#include <cuda_runtime.h>
#include <cuda_fp16.h>
#include <cstdint>

#define NN 100000      // input nodes
#define MM 100000      // output nodes
#define NNZ_C 3200000  // edges (divisible by 32)
#define BB 32          // batch
#define REPS 8         // fp16 accumulator replicas

// Scratch (uint4-typed for guaranteed 16B alignment)
__device__ uint4 g_xth4[NN * BB / 8];          // x_t (N,32) fp16, 6.4 MB
__device__ uint4 g_yth4[REPS * MM * BB / 8];   // 8 fp16 accum replicas, 51.2 MB

// ---------------------------------------------------------------------------
// Dummy no-op (keeps edge_kernel at ncu capture slot #3)
// ---------------------------------------------------------------------------
__global__ void dummy_kernel() {}

// ---------------------------------------------------------------------------
// Zero all replicas (uint4 grid-stride)
// ---------------------------------------------------------------------------
__global__ void zero_yt_kernel() {
    const int total = REPS * MM * BB / 8;   // 3.2M uint4
    uint4 z = make_uint4(0u, 0u, 0u, 0u);
    for (int i = blockIdx.x * blockDim.x + threadIdx.x; i < total;
         i += gridDim.x * blockDim.x) {
        g_yth4[i] = z;
    }
}

// ---------------------------------------------------------------------------
// Transpose x (B, N) -> x_t (N, B) in fp16.
// ---------------------------------------------------------------------------
__global__ void transpose_in_kernel(const float* __restrict__ x) {
    __shared__ float tile[128][33];
    __half* xth = (__half*)g_xth4;
    int n0 = blockIdx.x * 128;
    int t = threadIdx.x;
#pragma unroll
    for (int i = 0; i < 4; i++) {
        int idx = i * 256 + t;      // 0..1023
        int b = idx >> 5;           // batch row 0..31
        int q = idx & 31;           // float4 index along n
        int n = n0 + q * 4;
        if (n + 3 < NN) {
            float4 xv = __ldg((const float4*)(x + b * NN + n));
            tile[q * 4 + 0][b] = xv.x;
            tile[q * 4 + 1][b] = xv.y;
            tile[q * 4 + 2][b] = xv.z;
            tile[q * 4 + 3][b] = xv.w;
        } else {
#pragma unroll
            for (int j = 0; j < 4; j++)
                if (n + j < NN) tile[q * 4 + j][b] = x[b * NN + n + j];
        }
    }
    __syncthreads();
#pragma unroll
    for (int i = 0; i < 4; i++) {
        int idx = i * 256 + t;
        int nloc = idx >> 3;        // 0..127
        int b4 = idx & 7;
        int n = n0 + nloc;
        if (n < NN) {
            __half2 h0 = __floats2half2_rn(tile[nloc][b4 * 4 + 0],
                                           tile[nloc][b4 * 4 + 1]);
            __half2 h1 = __floats2half2_rn(tile[nloc][b4 * 4 + 2],
                                           tile[nloc][b4 * 4 + 3]);
            uint2 o;
            o.x = *(const unsigned int*)&h0;
            o.y = *(const unsigned int*)&h1;
            *(uint2*)(xth + n * BB + b4 * 4) = o;
        }
    }
}

// ---------------------------------------------------------------------------
// Edge scatter: 32 edges/warp. 4 lanes per edge (16B each), 8 edges per step.
// Gather: LDG.128 fp16; scale in HMUL2; scatter: red.add.noftz.v4.f16x2
// into replica (warp_id & 7). Interleaved loop (round-8 style).
// ---------------------------------------------------------------------------
__global__ void __launch_bounds__(256) edge_kernel(
        const int* __restrict__ src,
        const int* __restrict__ dst,
        const float* __restrict__ vals) {
    int gtid = blockIdx.x * blockDim.x + threadIdx.x;
    int warp_id = gtid >> 5;
    int lane = threadIdx.x & 31;

    int e = warp_id * 32 + lane;
    int   s = __ldg(&src[e]);
    int   d = __ldg(&dst[e]);
    float v = __ldg(&vals[e]);

    int seg = lane & 3;   // 16B chunk (8 halves) of the 64B batch row
    int sub = lane >> 2;  // which of 8 concurrent edges

    const uint4* xt4 = g_xth4;
    __half* ybase = (__half*)g_yth4 + (size_t)(warp_id & (REPS - 1)) * (MM * BB);

#pragma unroll
    for (int j = 0; j < 4; j++) {
        int eidx = j * 8 + sub;
        int   se = __shfl_sync(0xffffffffu, s, eidx);
        int   de = __shfl_sync(0xffffffffu, d, eidx);
        float ve = __shfl_sync(0xffffffffu, v, eidx);

        uint4 xv = __ldg(&xt4[se * 4 + seg]);       // 8 halves
        __half2 vv = __float2half2_rn(ve);
        __half2 a0 = __hmul2(*(const __half2*)&xv.x, vv);
        __half2 a1 = __hmul2(*(const __half2*)&xv.y, vv);
        __half2 a2 = __hmul2(*(const __half2*)&xv.z, vv);
        __half2 a3 = __hmul2(*(const __half2*)&xv.w, vv);

        __half* p = ybase + de * BB + seg * 8;      // 16B-aligned
        asm volatile(
            "red.global.add.noftz.v4.f16x2 [%0], {%1, %2, %3, %4};"
            :: "l"(p),
               "r"(*(const unsigned int*)&a0),
               "r"(*(const unsigned int*)&a1),
               "r"(*(const unsigned int*)&a2),
               "r"(*(const unsigned int*)&a3)
            : "memory");
    }
}

// ---------------------------------------------------------------------------
// out (B, M) = sum of 8 fp16 replicas (f32 accumulation) + bias, transposed.
// Phase 1: each thread sums 8 replicas for one (m, 8-batch-col chunk).
// Phase 2: conflict-free coalesced writeout.
// ---------------------------------------------------------------------------
__global__ void transpose_out_kernel(float* __restrict__ out,
                                     const float* __restrict__ bias) {
    __shared__ float tile[32][129];   // [b][m_local]
    int m0 = blockIdx.x * 128;
    int t = threadIdx.x;
    const int repstride = MM * BB / 8;   // uint4 per replica

#pragma unroll
    for (int i = 0; i < 2; i++) {
        int idx = i * 256 + t;      // 0..511
        int mloc = idx >> 2;        // 0..127
        int c = idx & 3;            // chunk: batch cols [c*8, c*8+8)
        int m = m0 + mloc;
        if (m < MM) {
            float acc[8];
#pragma unroll
            for (int k = 0; k < 8; k++) acc[k] = 0.f;
#pragma unroll
            for (int r = 0; r < REPS; r++) {
                uint4 yv = g_yth4[r * repstride + m * 4 + c];
                float2 f0 = __half22float2(*(const __half2*)&yv.x);
                float2 f1 = __half22float2(*(const __half2*)&yv.y);
                float2 f2 = __half22float2(*(const __half2*)&yv.z);
                float2 f3 = __half22float2(*(const __half2*)&yv.w);
                acc[0] += f0.x; acc[1] += f0.y;
                acc[2] += f1.x; acc[3] += f1.y;
                acc[4] += f2.x; acc[5] += f2.y;
                acc[6] += f3.x; acc[7] += f3.y;
            }
            float bi = __ldg(&bias[m]);
#pragma unroll
            for (int k = 0; k < 8; k++)
                tile[c * 8 + k][mloc] = acc[k] + bi;
        }
    }
    __syncthreads();
#pragma unroll
    for (int i = 0; i < 16; i++) {
        int idx = i * 256 + t;      // 0..4095
        int b  = idx >> 7;          // 0..31
        int ml = idx & 127;         // consecutive within warp
        int m = m0 + ml;
        if (m < MM)
            out[b * MM + m] = tile[b][ml];
    }
}

// ---------------------------------------------------------------------------
extern "C" void kernel_launch(void* const* d_in, const int* in_sizes, int n_in,
                              void* d_out, int out_size) {
    const float* x       = (const float*)d_in[0];   // (B, N, 1)
    const int*   indices = (const int*)d_in[1];     // (2, NNZ)
    const float* vals    = (const float*)d_in[2];   // (NNZ,)
    const float* bias    = (const float*)d_in[3];   // (M, 1)
    float* out = (float*)d_out;                     // (B, M, 1)

    const int* src = indices;
    const int* dst = indices + NNZ_C;

    // edge_kernel kept at launch index 3 for the ncu capture slot
    transpose_in_kernel<<<(NN + 127) / 128, 256>>>(x);          // 0
    zero_yt_kernel<<<3200, 256>>>();                            // 1
    dummy_kernel<<<1, 32>>>();                                  // 2
    edge_kernel<<<NNZ_C / 256, 256>>>(src, dst, vals);          // 3
    transpose_out_kernel<<<(MM + 127) / 128, 256>>>(out, bias); // 4
}